// round 5
// baseline (speedup 1.0000x reference)
#include <cuda_runtime.h>
#include <cuda_fp16.h>

#define NN 256
#define THREADS 512
#define ITERS 20

// smem union layout (bytes):
//   [0, 33792)      setup chunk Ksm (64 rows x 264 halves)  OR  redr (8448 floats)
//   [33792, 50688)  redc (4224 half2)
//   [50688, 51712)  Ah2 (256 half2)
//   [51712, 52224)  Bth2 (128 half2)
//   [52224, 53248)  Bf (256 float)
//   [53248, 54272)  Af (256 float)
#define SM_BYTES 54272

__global__ __launch_bounds__(THREADS, 1)
void sinkhorn_kernel(const float* __restrict__ x, float* __restrict__ out) {
    extern __shared__ char sm[];
    float*   redr = (float*)sm;
    __half2* redc = (__half2*)(sm + 33792);
    __half2* Ah2  = (__half2*)(sm + 50688);
    __half2* Bth2 = (__half2*)(sm + 51712);
    float*   Bf   = (float*)(sm + 52224);
    float*   Af   = (float*)(sm + 53248);
    __half*  Ksm  = (__half*)sm;          // setup staging (overlaps redr)
    uint4*   Ksm4 = (uint4*)sm;

    const int t = threadIdx.x;
    const int u = t & 31;          // uint4-column: halves 8u..8u+7 (half2 cols 4u..4u+3)
    const int s = t >> 5;          // row slice: rows 16s..16s+15 (s == warp id)
    const size_t base = (size_t)blockIdx.x * (NN * NN);
    const float* xm = x + base;
    float* om = out + base;

    uint4 kv[16];                  // register-resident K tile (fp16), whole kernel

    // ---------------- setup: 4 chunks of 64 rows through smem ----------------
    #pragma unroll
    for (int q = 0; q < 4; q++) {
        #pragma unroll
        for (int k = 0; k < 8; k++) {
            int idx = (k * THREADS + t) * 4;
            float4 v = *(const float4*)(xm + q * 64 * NN + idx);
            int ic = idx >> 8, j = idx & 255;
            *(__half2*)(Ksm + ic * 264 + j)     = __floats2half2_rn(__expf(v.x), __expf(v.y));
            *(__half2*)(Ksm + ic * 264 + j + 2) = __floats2half2_rn(__expf(v.z), __expf(v.w));
        }
        __syncthreads();
        if ((s >> 2) == q) {               // this thread's 16 rows live in this chunk
            #pragma unroll
            for (int r = 0; r < 16; r++)
                kv[r] = Ksm4[(16 * (s & 3) + r) * 33 + u];   // conflict-free
        }
        __syncthreads();
    }
    if (t < NN) Ah2[t] = __floats2half2_rn(1.0f, 1.0f);
    __syncthreads();

    // ---------------- main loop (linear-domain Sinkhorn) ----------------
    for (int it = 0; it < ITERS; it++) {
        // ===== column pass: partial col sums via HFMA2 (16-term half2 chains) =====
        uint4 av[4];                                         // A broadcast, 4x LDS.128
        const uint4* ap = (const uint4*)(Ah2 + 16 * s);      // warp-uniform, 16B-aligned
        av[0] = ap[0]; av[1] = ap[1]; av[2] = ap[2]; av[3] = ap[3];
        const __half2* a2v = (const __half2*)av;

        __half2 z = __floats2half2_rn(0.f, 0.f);
        __half2 acc0 = z, acc1 = z, acc2 = z, acc3 = z;
        #pragma unroll
        for (int r = 0; r < 16; r++) {
            __half2 a2 = a2v[r];
            const __half2* kh = (const __half2*)&kv[r];
            acc0 = __hfma2(kh[0], a2, acc0);
            acc1 = __hfma2(kh[1], a2, acc1);
            acc2 = __hfma2(kh[2], a2, acc2);
            acc3 = __hfma2(kh[3], a2, acc3);
        }
        redc[0 * 1056 + u * 33 + s] = acc0;   // bank = (u+s)%32, conflict-free
        redc[1 * 1056 + u * 33 + s] = acc1;
        redc[2 * 1056 + u * 33 + s] = acc2;
        redc[3 * 1056 + u * 33 + s] = acc3;
        __syncthreads();
        if (t < 128) {                         // fp32 cross-slice reduce + rcp
            int q = t >> 5, u2 = t & 31;
            const __half2* p = redc + q * 1056 + u2 * 33;    // stride 33, conflict-free
            float c0 = 0.f, c1 = 0.f;
            #pragma unroll
            for (int k = 0; k < 16; k++) {
                float2 f = __half22float2(p[k]);
                c0 += f.x; c1 += f.y;
            }
            float b0 = 1.0f / c0, b1 = 1.0f / c1;
            int j2 = 4 * u2 + q;
            Bth2[j2] = __floats2half2_rn(b0, b1);
            Bf[2 * j2]     = b0;
            Bf[2 * j2 + 1] = b1;
        }
        __syncthreads();

        // ===== row pass: per-row 8-col partials (4-term half2 chains -> fp32) =====
        uint4 bt = *(const uint4*)(Bth2 + 4 * u);            // LDS.128, conflict-free
        const __half2* b2 = (const __half2*)&bt;
        #pragma unroll
        for (int r = 0; r < 16; r++) {
            const __half2* kh = (const __half2*)&kv[r];
            __half2 pr = __hmul2(kh[0], b2[0]);
            pr = __hfma2(kh[1], b2[1], pr);
            pr = __hfma2(kh[2], b2[2], pr);
            pr = __hfma2(kh[3], b2[3], pr);
            float2 f = __half22float2(pr);
            redr[(16 * s + r) * 33 + u] = f.x + f.y;         // stride 33, conflict-free
        }
        __syncthreads();
        if (t < NN) {                          // fp32 cross-group reduce + rcp
            const float* p = redr + t * 33;
            float c0 = 0, c1 = 0, c2 = 0, c3 = 0;
            #pragma unroll
            for (int k = 0; k < 32; k += 4) {
                c0 += p[k]; c1 += p[k + 1]; c2 += p[k + 2]; c3 += p[k + 3];
            }
            float a = 1.0f / ((c0 + c1) + (c2 + c3));
            Ah2[t] = __floats2half2_rn(a, a);
            Af[t] = a;
        }
        __syncthreads();
    }

    // ---------------- epilogue: out = float(K_fp16) * A_i * B_j, from registers ----------------
    // Each warp owns full rows 16s..16s+15 -> perfectly coalesced STG.128 pairs.
    float4 bq0 = *(const float4*)(Bf + 8 * u);       // my 8 columns' B
    float4 bq1 = *(const float4*)(Bf + 8 * u + 4);
    #pragma unroll
    for (int r = 0; r < 16; r++) {
        float a = Af[16 * s + r];                    // warp-uniform broadcast
        const __half2* kh = (const __half2*)&kv[r];
        float2 f0 = __half22float2(kh[0]);
        float2 f1 = __half22float2(kh[1]);
        float2 f2 = __half22float2(kh[2]);
        float2 f3 = __half22float2(kh[3]);
        float4 o0, o1;
        o0.x = f0.x * a * bq0.x;  o0.y = f0.y * a * bq0.y;
        o0.z = f1.x * a * bq0.z;  o0.w = f1.y * a * bq0.w;
        o1.x = f2.x * a * bq1.x;  o1.y = f2.y * a * bq1.y;
        o1.z = f3.x * a * bq1.z;  o1.w = f3.y * a * bq1.w;
        float* op = om + (16 * s + r) * NN + 8 * u;
        *(float4*)op       = o0;
        *(float4*)(op + 4) = o1;
    }
}

extern "C" void kernel_launch(void* const* d_in, const int* in_sizes, int n_in,
                              void* d_out, int out_size) {
    const float* x = (const float*)d_in[0];
    float* out = (float*)d_out;
    int n_mat = in_sizes[0] / (NN * NN);      // 512
    cudaFuncSetAttribute(sinkhorn_kernel,
                         cudaFuncAttributeMaxDynamicSharedMemorySize, SM_BYTES);
    sinkhorn_kernel<<<n_mat, THREADS, SM_BYTES>>>(x, out);
}

// round 6
// speedup vs baseline: 1.0967x; 1.0967x over previous
#include <cuda_runtime.h>
#include <cuda_fp16.h>

#define NN 256
#define THREADS 512
#define ITERS 20

// smem union layout (bytes):
//   [0, 33792)      setup chunk Ksm (64 rows x 264 halves) OR redr (8448 floats)
//                   OR epilogue staging (64 rows x 32 uint4 = 32768 B)
//   [33792, 50688)  redc (4224 half2)
//   [50688, 51712)  Ah2 (256 half2)
//   [51712, 52224)  Bth2 (128 half2)
//   [52224, 53248)  Bf (256 float)
//   [53248, 54272)  Af (256 float)
#define SM_BYTES 54272

__global__ __launch_bounds__(THREADS, 1)
void sinkhorn_kernel(const float* __restrict__ x, float* __restrict__ out) {
    extern __shared__ char sm[];
    float*   redr = (float*)sm;
    __half2* redc = (__half2*)(sm + 33792);
    __half2* Ah2  = (__half2*)(sm + 50688);
    __half2* Bth2 = (__half2*)(sm + 51712);
    float*   Bf   = (float*)(sm + 52224);
    float*   Af   = (float*)(sm + 53248);
    __half*  Ksm  = (__half*)sm;          // setup staging (overlaps redr)
    uint4*   Ksm4 = (uint4*)sm;
    uint4*   Est4 = (uint4*)sm;           // epilogue staging (stride 32 uint4/row)
    uint2*   Est2 = (uint2*)sm;

    const int t = threadIdx.x;
    const int u = t & 31;          // uint4-column: halves 8u..8u+7 (half2 cols 4u..4u+3)
    const int s = t >> 5;          // row slice: rows 16s..16s+15 (s == warp id)
    const size_t base = (size_t)blockIdx.x * (NN * NN);
    const float* xm = x + base;
    float* om = out + base;

    uint4 kv[16];                  // register-resident K tile (fp16), whole kernel

    // ---------------- setup: 4 chunks of 64 rows through smem ----------------
    #pragma unroll
    for (int q = 0; q < 4; q++) {
        #pragma unroll
        for (int k = 0; k < 8; k++) {
            int idx = (k * THREADS + t) * 4;
            float4 v = *(const float4*)(xm + q * 64 * NN + idx);
            int ic = idx >> 8, j = idx & 255;
            *(__half2*)(Ksm + ic * 264 + j)     = __floats2half2_rn(__expf(v.x), __expf(v.y));
            *(__half2*)(Ksm + ic * 264 + j + 2) = __floats2half2_rn(__expf(v.z), __expf(v.w));
        }
        __syncthreads();
        if ((s >> 2) == q) {               // this thread's 16 rows live in this chunk
            #pragma unroll
            for (int r = 0; r < 16; r++)
                kv[r] = Ksm4[(16 * (s & 3) + r) * 33 + u];   // conflict-free
        }
        __syncthreads();
    }
    if (t < NN) Ah2[t] = __floats2half2_rn(1.0f, 1.0f);
    __syncthreads();

    // ---------------- main loop (linear-domain Sinkhorn) ----------------
    for (int it = 0; it < ITERS; it++) {
        // ===== column pass: partial col sums via HFMA2 (16-term half2 chains) =====
        __half2 z = __floats2half2_rn(0.f, 0.f);
        __half2 acc0 = z, acc1 = z, acc2 = z, acc3 = z;
        #pragma unroll
        for (int r = 0; r < 16; r++) {
            __half2 a2 = Ah2[16 * s + r];                    // warp-uniform broadcast
            const __half2* kh = (const __half2*)&kv[r];
            acc0 = __hfma2(kh[0], a2, acc0);
            acc1 = __hfma2(kh[1], a2, acc1);
            acc2 = __hfma2(kh[2], a2, acc2);
            acc3 = __hfma2(kh[3], a2, acc3);
        }
        redc[0 * 1056 + u * 33 + s] = acc0;   // bank = (u+s)%32, conflict-free
        redc[1 * 1056 + u * 33 + s] = acc1;
        redc[2 * 1056 + u * 33 + s] = acc2;
        redc[3 * 1056 + u * 33 + s] = acc3;
        __syncthreads();
        if (t < 128) {                         // fp32 cross-slice reduce + rcp
            int q = t >> 5, u2 = t & 31;
            const __half2* p = redc + q * 1056 + u2 * 33;    // stride 33, conflict-free
            float c0 = 0.f, c1 = 0.f;
            #pragma unroll
            for (int k = 0; k < 16; k++) {
                float2 f = __half22float2(p[k]);
                c0 += f.x; c1 += f.y;
            }
            float b0 = 1.0f / c0, b1 = 1.0f / c1;
            int j2 = 4 * u2 + q;
            Bth2[j2] = __floats2half2_rn(b0, b1);
            Bf[2 * j2]     = b0;
            Bf[2 * j2 + 1] = b1;
        }
        __syncthreads();

        // ===== row pass: per-row 8-col partials (4-term half2 chains -> fp32) =====
        uint4 bt = *(const uint4*)(Bth2 + 4 * u);            // LDS.128, conflict-free
        const __half2* b2 = (const __half2*)&bt;
        #pragma unroll
        for (int r = 0; r < 16; r++) {
            const __half2* kh = (const __half2*)&kv[r];
            __half2 pr = __hmul2(kh[0], b2[0]);
            pr = __hfma2(kh[1], b2[1], pr);
            pr = __hfma2(kh[2], b2[2], pr);
            pr = __hfma2(kh[3], b2[3], pr);
            float2 f = __half22float2(pr);
            redr[(16 * s + r) * 33 + u] = f.x + f.y;         // stride 33, conflict-free
        }
        __syncthreads();
        if (t < NN) {                          // fp32 cross-group reduce + rcp
            const float* p = redr + t * 33;
            float c0 = 0, c1 = 0, c2 = 0, c3 = 0;
            #pragma unroll
            for (int k = 0; k < 32; k += 4) {
                c0 += p[k]; c1 += p[k + 1]; c2 += p[k + 2]; c3 += p[k + 3];
            }
            float a = 1.0f / ((c0 + c1) + (c2 + c3));
            Ah2[t] = __floats2half2_rn(a, a);
            Af[t] = a;
        }
        __syncthreads();
    }

    // ---------------- epilogue: register K -> smem transpose -> coalesced STG ----------------
    // My column group for the coalesced read/store phase is invariant across chunks.
    const int cc = (s & 1) * 32 + u;                 // uint2 column 0..63 (= float4 col)
    const float4 bq = *(const float4*)(Bf + 4 * cc); // B for my 4 output columns
    #pragma unroll
    for (int q = 0; q < 4; q++) {
        __syncthreads();                             // chunk q-1 readers done
        if ((s >> 2) == q) {                         // stage my 16 rows (STS.128, bank 4u: conflict-free)
            #pragma unroll
            for (int r = 0; r < 16; r++)
                Est4[(16 * (s & 3) + r) * 32 + u] = kv[r];
        }
        __syncthreads();
        #pragma unroll
        for (int k = 0; k < 8; k++) {                // linear LDS.64, conflict-free (2-phase)
            int rc = k * 8 + (s >> 1);               // row within chunk 0..63
            uint2 kk = Est2[rc * 64 + cc];
            float ai = Af[64 * q + rc];              // warp-uniform broadcast
            float2 f0 = __half22float2(*(__half2*)&kk.x);
            float2 f1 = __half22float2(*(__half2*)&kk.y);
            float4 o;
            o.x = f0.x * ai * bq.x;
            o.y = f0.y * ai * bq.y;
            o.z = f1.x * ai * bq.z;
            o.w = f1.y * ai * bq.w;
            *(float4*)(om + (64 * q + rc) * NN + 4 * cc) = o;   // contiguous 512B/warp
        }
    }
}

extern "C" void kernel_launch(void* const* d_in, const int* in_sizes, int n_in,
                              void* d_out, int out_size) {
    const float* x = (const float*)d_in[0];
    float* out = (float*)d_out;
    int n_mat = in_sizes[0] / (NN * NN);      // 512
    cudaFuncSetAttribute(sinkhorn_kernel,
                         cudaFuncAttributeMaxDynamicSharedMemorySize, SM_BYTES);
    sinkhorn_kernel<<<n_mat, THREADS, SM_BYTES>>>(x, out);
}

// round 7
// speedup vs baseline: 1.4242x; 1.2986x over previous
#include <cuda_runtime.h>
#include <cuda_fp16.h>

#define NN 256
#define THREADS 512
#define ITERS 20
#define TOL 1e-4f

// smem union layout (bytes):
//   [0, 33792)      setup chunk Ksm (64 rows x 264 halves) OR redr (8448 floats)
//                   OR epilogue staging (64 rows x 32 uint4 = 32768 B)
//   [33792, 50688)  redc (4224 half2)
//   [50688, 51712)  Ah2 (256 half2)
//   [51712, 52224)  Bth2 (128 half2)
//   [52224, 53248)  Bf (256 float)
//   [53248, 54272)  Af (256 float)
//   [54272, 54280)  flags[2] (convergence, double-buffered)
#define SM_BYTES 54288

__global__ __launch_bounds__(THREADS, 1)
void sinkhorn_kernel(const float* __restrict__ x, float* __restrict__ out) {
    extern __shared__ char sm[];
    float*   redr  = (float*)sm;
    __half2* redc  = (__half2*)(sm + 33792);
    __half2* Ah2   = (__half2*)(sm + 50688);
    __half2* Bth2  = (__half2*)(sm + 51712);
    float*   Bf    = (float*)(sm + 52224);
    float*   Af    = (float*)(sm + 53248);
    int*     flags = (int*)(sm + 54272);
    __half*  Ksm   = (__half*)sm;          // setup staging (overlaps redr)
    uint4*   Ksm4  = (uint4*)sm;
    uint4*   Est4  = (uint4*)sm;           // epilogue staging (stride 32 uint4/row)
    uint2*   Est2  = (uint2*)sm;

    const int t = threadIdx.x;
    const int u = t & 31;          // uint4-column: halves 8u..8u+7 (half2 cols 4u..4u+3)
    const int s = t >> 5;          // row slice: rows 16s..16s+15 (s == warp id)
    const size_t base = (size_t)blockIdx.x * (NN * NN);
    const float* xm = x + base;
    float* om = out + base;

    uint4 kv[16];                  // register-resident K tile (fp16), whole kernel

    // ---------------- setup: 4 chunks of 64 rows through smem ----------------
    #pragma unroll
    for (int q = 0; q < 4; q++) {
        #pragma unroll
        for (int k = 0; k < 8; k++) {
            int idx = (k * THREADS + t) * 4;
            float4 v = *(const float4*)(xm + q * 64 * NN + idx);
            int ic = idx >> 8, j = idx & 255;
            *(__half2*)(Ksm + ic * 264 + j)     = __floats2half2_rn(__expf(v.x), __expf(v.y));
            *(__half2*)(Ksm + ic * 264 + j + 2) = __floats2half2_rn(__expf(v.z), __expf(v.w));
        }
        __syncthreads();
        if ((s >> 2) == q) {               // this thread's 16 rows live in this chunk
            #pragma unroll
            for (int r = 0; r < 16; r++)
                kv[r] = Ksm4[(16 * (s & 3) + r) * 33 + u];   // conflict-free
        }
        __syncthreads();
    }
    if (t < NN) { Ah2[t] = __floats2half2_rn(1.0f, 1.0f); Af[t] = 1.0f; }
    if (t == 0) { flags[0] = 0; flags[1] = 0; }
    __syncthreads();

    // ---------------- main loop (linear-domain Sinkhorn, adaptive exit) ----------------
    for (int it = 0; it < ITERS; it++) {
        // ===== column pass: partial col sums via HFMA2 (16-term half2 chains) =====
        __half2 z = __floats2half2_rn(0.f, 0.f);
        __half2 acc0 = z, acc1 = z, acc2 = z, acc3 = z;
        #pragma unroll
        for (int r = 0; r < 16; r++) {
            __half2 a2 = Ah2[16 * s + r];                    // warp-uniform broadcast
            const __half2* kh = (const __half2*)&kv[r];
            acc0 = __hfma2(kh[0], a2, acc0);
            acc1 = __hfma2(kh[1], a2, acc1);
            acc2 = __hfma2(kh[2], a2, acc2);
            acc3 = __hfma2(kh[3], a2, acc3);
        }
        redc[0 * 1056 + u * 33 + s] = acc0;   // bank = (u+s)%32, conflict-free
        redc[1 * 1056 + u * 33 + s] = acc1;
        redc[2 * 1056 + u * 33 + s] = acc2;
        redc[3 * 1056 + u * 33 + s] = acc3;
        __syncthreads();
        if (t < 128) {                         // fp32 cross-slice reduce + rcp (4 accs)
            if (t == 0) flags[(it + 1) & 1] = 0;   // reset next-parity flag (barrier-separated)
            int q = t >> 5, u2 = t & 31;
            const __half2* p = redc + q * 1056 + u2 * 33;    // stride 33, conflict-free
            float c0a = 0.f, c0b = 0.f, c1a = 0.f, c1b = 0.f;
            #pragma unroll
            for (int k = 0; k < 16; k += 2) {
                float2 f0 = __half22float2(p[k]);
                float2 f1 = __half22float2(p[k + 1]);
                c0a += f0.x; c1a += f0.y;
                c0b += f1.x; c1b += f1.y;
            }
            float b0 = 1.0f / (c0a + c0b), b1 = 1.0f / (c1a + c1b);
            int j2 = 4 * u2 + q;
            Bth2[j2] = __floats2half2_rn(b0, b1);
            Bf[2 * j2]     = b0;
            Bf[2 * j2 + 1] = b1;
        }
        __syncthreads();

        // ===== row pass: per-row 8-col partials (4-term half2 chains -> fp32) =====
        uint4 bt = *(const uint4*)(Bth2 + 4 * u);            // LDS.128, conflict-free
        const __half2* b2 = (const __half2*)&bt;
        #pragma unroll
        for (int r = 0; r < 16; r++) {
            const __half2* kh = (const __half2*)&kv[r];
            __half2 pr = __hmul2(kh[0], b2[0]);
            pr = __hfma2(kh[1], b2[1], pr);
            pr = __hfma2(kh[2], b2[2], pr);
            pr = __hfma2(kh[3], b2[3], pr);
            float2 f = __half22float2(pr);
            redr[(16 * s + r) * 33 + u] = f.x + f.y;         // stride 33, conflict-free
        }
        __syncthreads();
        if (t < NN) {                          // fp32 cross-group reduce + rcp
            const float* p = redr + t * 33;
            float c0 = 0, c1 = 0, c2 = 0, c3 = 0;
            #pragma unroll
            for (int k = 0; k < 32; k += 4) {
                c0 += p[k]; c1 += p[k + 1]; c2 += p[k + 2]; c3 += p[k + 3];
            }
            float a = 1.0f / ((c0 + c1) + (c2 + c3));
            float prev = Af[t];
            if (fabsf(a - prev) > TOL * prev) flags[it & 1] = 1;  // benign race (same value)
            Ah2[t] = __floats2half2_rn(a, a);
            Af[t] = a;
        }
        __syncthreads();
        if (flags[it & 1] == 0) break;         // converged: further iters move output < ~1.5e-4
    }

    // ---------------- epilogue: register K -> smem transpose -> coalesced STG ----------------
    const int cc = (s & 1) * 32 + u;                 // uint2 column 0..63 (= float4 col)
    const float4 bq = *(const float4*)(Bf + 4 * cc); // B for my 4 output columns
    #pragma unroll
    for (int q = 0; q < 4; q++) {
        __syncthreads();                             // chunk q-1 readers done
        if ((s >> 2) == q) {                         // stage my 16 rows (STS.128, conflict-free)
            #pragma unroll
            for (int r = 0; r < 16; r++)
                Est4[(16 * (s & 3) + r) * 32 + u] = kv[r];
        }
        __syncthreads();
        #pragma unroll
        for (int k = 0; k < 8; k++) {                // linear LDS.64, conflict-free (2-phase)
            int rc = k * 8 + (s >> 1);               // row within chunk 0..63
            uint2 kk = Est2[rc * 64 + cc];
            float ai = Af[64 * q + rc];              // warp-uniform broadcast
            float2 f0 = __half22float2(*(__half2*)&kk.x);
            float2 f1 = __half22float2(*(__half2*)&kk.y);
            float4 o;
            o.x = f0.x * ai * bq.x;
            o.y = f0.y * ai * bq.y;
            o.z = f1.x * ai * bq.z;
            o.w = f1.y * ai * bq.w;
            *(float4*)(om + (64 * q + rc) * NN + 4 * cc) = o;   // contiguous 512B/warp
        }
    }
}

extern "C" void kernel_launch(void* const* d_in, const int* in_sizes, int n_in,
                              void* d_out, int out_size) {
    const float* x = (const float*)d_in[0];
    float* out = (float*)d_out;
    int n_mat = in_sizes[0] / (NN * NN);      // 512
    cudaFuncSetAttribute(sinkhorn_kernel,
                         cudaFuncAttributeMaxDynamicSharedMemorySize, SM_BYTES);
    sinkhorn_kernel<<<n_mat, THREADS, SM_BYTES>>>(x, out);
}

// round 8
// speedup vs baseline: 2.2656x; 1.5908x over previous
#include <cuda_runtime.h>
#include <cuda_fp16.h>

#define NN 256
#define THREADS 256
#define ITERS 20
#define TOL 2e-4f

// smem layout (bytes), per CTA total 109576 (x2 CTAs = 219152 <= 228KB/SM):
//   [0,      67584)  Ksm: rows 128..255, 128 x 33 uint4 (264 halves/row)
//   [67584,  72192)  redc: 4 x 288 half2 (col partials, 8 slices, stride 9)
//   [72192, 105984)  redr: 8448 floats (row partials)  OR setup/epilogue staging (64 x 33 uint4)
//   [105984,107008)  Ah2: 256 half2
//   [107008,107520)  Bth2: 128 half2
//   [107520,108544)  Bf: 256 float
//   [108544,109568)  Af: 256 float
//   [109568,109576)  flags[2]
#define SM_BYTES 109576

__global__ __launch_bounds__(THREADS, 2)
void sinkhorn_kernel(const float* __restrict__ x, float* __restrict__ out) {
    extern __shared__ char sm[];
    __half*  Ksm   = (__half*)sm;
    __half2* Ksm2  = (__half2*)sm;
    uint4*   Ksm4  = (uint4*)sm;
    __half2* redc  = (__half2*)(sm + 67584);
    float*   redr  = (float*)(sm + 72192);
    __half*  stgH  = (__half*)(sm + 72192);     // staging overlaps redr
    uint4*   stg4  = (uint4*)(sm + 72192);
    __half2* stg2  = (__half2*)(sm + 72192);
    __half2* Ah2   = (__half2*)(sm + 105984);
    __half2* Bth2  = (__half2*)(sm + 107008);
    float*   Bf    = (float*)(sm + 107520);
    float*   Af    = (float*)(sm + 108544);
    int*     flags = (int*)(sm + 109568);

    const int t = threadIdx.x;
    const int l = t & 31;          // lane: owns halves 8l..8l+7 of its rows
    const int w = t >> 5;          // warp 0..7: reg rows 16w..16w+15, smem rows 128+16w..+15
    const size_t base = (size_t)blockIdx.x * (NN * NN);
    const float* xm = x + base;
    float* om = out + base;

    uint4 kv[16];                  // register half: rows 16w..16w+15, fp16

    // ---------------- setup: reg half (rows 0..127) via staging ----------------
    #pragma unroll
    for (int c = 0; c < 2; c++) {
        #pragma unroll
        for (int k = 0; k < 16; k++) {
            int idx = (k * THREADS + t) * 4;
            float4 v = *(const float4*)(xm + c * 64 * NN + idx);
            int i = idx >> 8, j = idx & 255;
            *(__half2*)(stgH + i * 264 + j)     = __floats2half2_rn(__expf(v.x), __expf(v.y));
            *(__half2*)(stgH + i * 264 + j + 2) = __floats2half2_rn(__expf(v.z), __expf(v.w));
        }
        __syncthreads();
        if ((w >> 2) == c) {
            #pragma unroll
            for (int r = 0; r < 16; r++)
                kv[r] = stg4[(16 * (w & 3) + r) * 33 + l];   // contiguous per row: conflict-free
        }
        __syncthreads();
    }
    // ---------------- setup: smem half (rows 128..255) direct ----------------
    #pragma unroll
    for (int c = 0; c < 2; c++) {
        #pragma unroll
        for (int k = 0; k < 16; k++) {
            int idx = (k * THREADS + t) * 4;
            float4 v = *(const float4*)(xm + (128 + c * 64) * NN + idx);
            int i = idx >> 8, j = idx & 255;
            int srow = c * 64 + i;
            *(__half2*)(Ksm + srow * 264 + j)     = __floats2half2_rn(__expf(v.x), __expf(v.y));
            *(__half2*)(Ksm + srow * 264 + j + 2) = __floats2half2_rn(__expf(v.z), __expf(v.w));
        }
    }
    if (t < NN) { Ah2[t] = __floats2half2_rn(1.0f, 1.0f); Af[t] = 1.0f; }
    if (t == 0) { flags[0] = 0; flags[1] = 0; }
    __syncthreads();

    // ---------------- main loop ----------------
    for (int it = 0; it < ITERS; it++) {
        // ===== column pass: 32 rows/thread (16 reg + 16 smem) =====
        __half2 z = __floats2half2_rn(0.f, 0.f);
        __half2 acc0 = z, acc1 = z, acc2 = z, acc3 = z;
        #pragma unroll
        for (int r = 0; r < 16; r++) {
            __half2 a2 = Ah2[16 * w + r];                     // warp-uniform
            const __half2* kh = (const __half2*)&kv[r];
            acc0 = __hfma2(kh[0], a2, acc0);
            acc1 = __hfma2(kh[1], a2, acc1);
            acc2 = __hfma2(kh[2], a2, acc2);
            acc3 = __hfma2(kh[3], a2, acc3);
            uint4 ks = Ksm4[(16 * w + r) * 33 + l];           // contiguous: conflict-free
            __half2 a2s = Ah2[128 + 16 * w + r];
            const __half2* khs = (const __half2*)&ks;
            acc0 = __hfma2(khs[0], a2s, acc0);
            acc1 = __hfma2(khs[1], a2s, acc1);
            acc2 = __hfma2(khs[2], a2s, acc2);
            acc3 = __hfma2(khs[3], a2s, acc3);
        }
        redc[0 * 288 + l * 9 + w] = acc0;   // bank = (9l+w)%32: conflict-free
        redc[1 * 288 + l * 9 + w] = acc1;
        redc[2 * 288 + l * 9 + w] = acc2;
        redc[3 * 288 + l * 9 + w] = acc3;
        __syncthreads();
        if (t < 128) {                       // fp32 reduce over 8 slices + rcp
            if (t == 0) flags[(it + 1) & 1] = 0;
            int e = t >> 5, u2 = t & 31;
            const __half2* p = redc + e * 288 + u2 * 9;       // bank (9u2+k): conflict-free
            float c0a = 0.f, c0b = 0.f, c1a = 0.f, c1b = 0.f;
            #pragma unroll
            for (int k = 0; k < 8; k += 2) {
                float2 f0 = __half22float2(p[k]);
                float2 f1 = __half22float2(p[k + 1]);
                c0a += f0.x; c1a += f0.y;
                c0b += f1.x; c1b += f1.y;
            }
            float b0 = 1.0f / (c0a + c0b), b1 = 1.0f / (c1a + c1b);
            int j2 = 4 * u2 + e;
            Bth2[j2] = __floats2half2_rn(b0, b1);
            Bf[2 * j2]     = b0;
            Bf[2 * j2 + 1] = b1;
        }
        __syncthreads();

        // ===== row pass: 32 rows/thread =====
        uint4 bt = *(const uint4*)(Bth2 + 4 * l);             // LDS.128, conflict-free
        const __half2* b2 = (const __half2*)&bt;
        #pragma unroll
        for (int r = 0; r < 16; r++) {
            const __half2* kh = (const __half2*)&kv[r];
            __half2 pr = __hmul2(kh[0], b2[0]);
            pr = __hfma2(kh[1], b2[1], pr);
            pr = __hfma2(kh[2], b2[2], pr);
            pr = __hfma2(kh[3], b2[3], pr);
            float2 f = __half22float2(pr);
            redr[(16 * w + r) * 33 + l] = f.x + f.y;          // bank l: conflict-free

            uint4 ks = Ksm4[(16 * w + r) * 33 + l];
            const __half2* khs = (const __half2*)&ks;
            __half2 ps = __hmul2(khs[0], b2[0]);
            ps = __hfma2(khs[1], b2[1], ps);
            ps = __hfma2(khs[2], b2[2], ps);
            ps = __hfma2(khs[3], b2[3], ps);
            float2 fs = __half22float2(ps);
            redr[(128 + 16 * w + r) * 33 + l] = fs.x + fs.y;
        }
        __syncthreads();
        {                                    // all 256 threads: row i = t
            const float* p = redr + t * 33;  // bank (t+k): conflict-free
            float c0 = 0, c1 = 0, c2 = 0, c3 = 0;
            #pragma unroll
            for (int k = 0; k < 32; k += 4) {
                c0 += p[k]; c1 += p[k + 1]; c2 += p[k + 2]; c3 += p[k + 3];
            }
            float a = 1.0f / ((c0 + c1) + (c2 + c3));
            float prev = Af[t];
            if (fabsf(a - prev) > TOL * prev) flags[it & 1] = 1;   // benign race
            Ah2[t] = __floats2half2_rn(a, a);
            Af[t] = a;
        }
        __syncthreads();
        if (flags[it & 1] == 0) break;
    }

    // ---------------- epilogue ----------------
    const int cc = t & 63;                            // my float4 column group (fixed)
    const float4 bq = *(const float4*)(Bf + 4 * cc);

    // smem half (rows 128..255): direct, coalesced (512B/warp STG)
    #pragma unroll
    for (int k = 0; k < 32; k++) {
        int rc = k * 4 + (t >> 6);                    // row 0..127 (warp-uniform)
        __half2 h0 = Ksm2[rc * 132 + 2 * cc];
        __half2 h1 = Ksm2[rc * 132 + 2 * cc + 1];
        float ai = Af[128 + rc];
        float2 f0 = __half22float2(h0);
        float2 f1 = __half22float2(h1);
        float4 o;
        o.x = f0.x * ai * bq.x;
        o.y = f0.y * ai * bq.y;
        o.z = f1.x * ai * bq.z;
        o.w = f1.y * ai * bq.w;
        *(float4*)(om + (128 + rc) * NN + 4 * cc) = o;
    }
    // reg half (rows 0..127): via staging transpose, 2 chunks of 64 rows
    #pragma unroll
    for (int c = 0; c < 2; c++) {
        __syncthreads();
        if ((w >> 2) == c) {
            #pragma unroll
            for (int r = 0; r < 16; r++)
                stg4[(16 * (w & 3) + r) * 33 + l] = kv[r];    // conflict-free
        }
        __syncthreads();
        #pragma unroll
        for (int k = 0; k < 16; k++) {
            int rc = k * 4 + (t >> 6);                // row-in-chunk 0..63 (warp-uniform)
            __half2 h0 = stg2[rc * 132 + 2 * cc];
            __half2 h1 = stg2[rc * 132 + 2 * cc + 1];
            float ai = Af[c * 64 + rc];
            float2 f0 = __half22float2(h0);
            float2 f1 = __half22float2(h1);
            float4 o;
            o.x = f0.x * ai * bq.x;
            o.y = f0.y * ai * bq.y;
            o.z = f1.x * ai * bq.z;
            o.w = f1.y * ai * bq.w;
            *(float4*)(om + (c * 64 + rc) * NN + 4 * cc) = o;
        }
    }
}

extern "C" void kernel_launch(void* const* d_in, const int* in_sizes, int n_in,
                              void* d_out, int out_size) {
    const float* x = (const float*)d_in[0];
    float* out = (float*)d_out;
    int n_mat = in_sizes[0] / (NN * NN);      // 512
    cudaFuncSetAttribute(sinkhorn_kernel,
                         cudaFuncAttributeMaxDynamicSharedMemorySize, SM_BYTES);
    sinkhorn_kernel<<<n_mat, THREADS, SM_BYTES>>>(x, out);
}

// round 9
// speedup vs baseline: 2.3540x; 1.0390x over previous
#include <cuda_runtime.h>
#include <cuda_fp16.h>

#define NN 256
#define THREADS 256
#define ITERS 20
#define TOL 4e-4f

// smem layout (bytes), per CTA total 109576 (x2 CTAs = 219152 <= 228KB/SM):
//   [0,      67584)  Ksm: rows 128..255, 128 x 33 uint4 (264 halves/row)
//   [67584,  72192)  redc: 4 x 288 half2 (col partials, 8 slices, stride 9)
//   [72192, 105984)  redr: 8448 floats (row partials)  OR epilogue staging (64 x 33 uint4)
//   [105984,107008)  Ah2: 256 half2
//   [107008,107520)  Bth2: 128 half2
//   [107520,108544)  Bf: 256 float
//   [108544,109568)  Af: 256 float
//   [109568,109576)  flags[2]
#define SM_BYTES 109576

__global__ __launch_bounds__(THREADS, 2)
void sinkhorn_kernel(const float* __restrict__ x, float* __restrict__ out) {
    extern __shared__ char sm[];
    __half*  Ksm   = (__half*)sm;
    __half2* Ksm2  = (__half2*)sm;
    uint4*   Ksm4  = (uint4*)sm;
    __half2* redc  = (__half2*)(sm + 67584);
    float*   redr  = (float*)(sm + 72192);
    uint4*   stg4  = (uint4*)(sm + 72192);      // epilogue staging overlaps redr
    __half2* stg2  = (__half2*)(sm + 72192);
    __half2* Ah2   = (__half2*)(sm + 105984);
    __half2* Bth2  = (__half2*)(sm + 107008);
    float*   Bf    = (float*)(sm + 107520);
    float*   Af    = (float*)(sm + 108544);
    int*     flags = (int*)(sm + 109568);

    const int t = threadIdx.x;
    const int l = t & 31;          // lane: owns halves 8l..8l+7 of its rows
    const int w = t >> 5;          // warp 0..7: reg rows 16w..16w+15, smem rows 128+16w..+15
    const size_t base = (size_t)blockIdx.x * (NN * NN);
    const float* xm = x + base;
    float* om = out + base;

    uint4 kv[16];                  // register half: rows 16w..16w+15, fp16

    // ---------------- setup: reg half (rows 0..127) DIRECT gmem->reg, no barriers ----
    // Warp w row r: 32 lanes read 32B each (2x LDG.128, 32B lane stride) = full 1KB row.
    #pragma unroll
    for (int r = 0; r < 16; r++) {
        const float* rp = xm + (16 * w + r) * NN + 8 * l;
        float4 v0 = *(const float4*)rp;
        float4 v1 = *(const float4*)(rp + 4);
        __half2 h0 = __floats2half2_rn(__expf(v0.x), __expf(v0.y));
        __half2 h1 = __floats2half2_rn(__expf(v0.z), __expf(v0.w));
        __half2 h2 = __floats2half2_rn(__expf(v1.x), __expf(v1.y));
        __half2 h3 = __floats2half2_rn(__expf(v1.z), __expf(v1.w));
        kv[r].x = *(unsigned*)&h0;
        kv[r].y = *(unsigned*)&h1;
        kv[r].z = *(unsigned*)&h2;
        kv[r].w = *(unsigned*)&h3;
    }
    // ---------------- setup: smem half (rows 128..255) direct, coalesced ----------------
    #pragma unroll
    for (int c = 0; c < 2; c++) {
        #pragma unroll
        for (int k = 0; k < 16; k++) {
            int idx = (k * THREADS + t) * 4;
            float4 v = *(const float4*)(xm + (128 + c * 64) * NN + idx);
            int i = idx >> 8, j = idx & 255;
            int srow = c * 64 + i;
            *(__half2*)(Ksm + srow * 264 + j)     = __floats2half2_rn(__expf(v.x), __expf(v.y));
            *(__half2*)(Ksm + srow * 264 + j + 2) = __floats2half2_rn(__expf(v.z), __expf(v.w));
        }
    }
    if (t < NN) { Ah2[t] = __floats2half2_rn(1.0f, 1.0f); Af[t] = 1.0f; }
    if (t == 0) { flags[0] = 0; flags[1] = 0; }
    __syncthreads();

    // ---------------- main loop ----------------
    for (int it = 0; it < ITERS; it++) {
        // ===== column pass: 32 rows/thread (16 reg + 16 smem) =====
        __half2 z = __floats2half2_rn(0.f, 0.f);
        __half2 acc0 = z, acc1 = z, acc2 = z, acc3 = z;
        #pragma unroll
        for (int r = 0; r < 16; r++) {
            __half2 a2 = Ah2[16 * w + r];                     // warp-uniform
            const __half2* kh = (const __half2*)&kv[r];
            acc0 = __hfma2(kh[0], a2, acc0);
            acc1 = __hfma2(kh[1], a2, acc1);
            acc2 = __hfma2(kh[2], a2, acc2);
            acc3 = __hfma2(kh[3], a2, acc3);
            uint4 ks = Ksm4[(16 * w + r) * 33 + l];           // contiguous: conflict-free
            __half2 a2s = Ah2[128 + 16 * w + r];
            const __half2* khs = (const __half2*)&ks;
            acc0 = __hfma2(khs[0], a2s, acc0);
            acc1 = __hfma2(khs[1], a2s, acc1);
            acc2 = __hfma2(khs[2], a2s, acc2);
            acc3 = __hfma2(khs[3], a2s, acc3);
        }
        redc[0 * 288 + l * 9 + w] = acc0;   // bank = (9l+w)%32: conflict-free
        redc[1 * 288 + l * 9 + w] = acc1;
        redc[2 * 288 + l * 9 + w] = acc2;
        redc[3 * 288 + l * 9 + w] = acc3;
        __syncthreads();
        if (t < 128) {                       // fp32 reduce over 8 slices + rcp
            if (t == 0) flags[(it + 1) & 1] = 0;
            int e = t >> 5, u2 = t & 31;
            const __half2* p = redc + e * 288 + u2 * 9;       // conflict-free
            float c0a = 0.f, c0b = 0.f, c1a = 0.f, c1b = 0.f;
            #pragma unroll
            for (int k = 0; k < 8; k += 2) {
                float2 f0 = __half22float2(p[k]);
                float2 f1 = __half22float2(p[k + 1]);
                c0a += f0.x; c1a += f0.y;
                c0b += f1.x; c1b += f1.y;
            }
            float b0 = 1.0f / (c0a + c0b), b1 = 1.0f / (c1a + c1b);
            int j2 = 4 * u2 + e;
            Bth2[j2] = __floats2half2_rn(b0, b1);
            Bf[2 * j2]     = b0;
            Bf[2 * j2 + 1] = b1;
        }
        __syncthreads();

        // ===== row pass: 32 rows/thread =====
        uint4 bt = *(const uint4*)(Bth2 + 4 * l);             // LDS.128, conflict-free
        const __half2* b2 = (const __half2*)&bt;
        #pragma unroll
        for (int r = 0; r < 16; r++) {
            const __half2* kh = (const __half2*)&kv[r];
            __half2 pr = __hmul2(kh[0], b2[0]);
            pr = __hfma2(kh[1], b2[1], pr);
            pr = __hfma2(kh[2], b2[2], pr);
            pr = __hfma2(kh[3], b2[3], pr);
            float2 f = __half22float2(pr);
            redr[(16 * w + r) * 33 + l] = f.x + f.y;          // conflict-free

            uint4 ks = Ksm4[(16 * w + r) * 33 + l];
            const __half2* khs = (const __half2*)&ks;
            __half2 ps = __hmul2(khs[0], b2[0]);
            ps = __hfma2(khs[1], b2[1], ps);
            ps = __hfma2(khs[2], b2[2], ps);
            ps = __hfma2(khs[3], b2[3], ps);
            float2 fs = __half22float2(ps);
            redr[(128 + 16 * w + r) * 33 + l] = fs.x + fs.y;
        }
        __syncthreads();
        {                                    // all 256 threads: row i = t
            const float* p = redr + t * 33;  // conflict-free
            float c0 = 0, c1 = 0, c2 = 0, c3 = 0;
            #pragma unroll
            for (int k = 0; k < 32; k += 4) {
                c0 += p[k]; c1 += p[k + 1]; c2 += p[k + 2]; c3 += p[k + 3];
            }
            float a = 1.0f / ((c0 + c1) + (c2 + c3));
            float prev = Af[t];
            if (fabsf(a - prev) > TOL * prev) flags[it & 1] = 1;   // benign race
            Ah2[t] = __floats2half2_rn(a, a);
            Af[t] = a;
        }
        __syncthreads();
        if (flags[it & 1] == 0) break;
    }

    // ---------------- epilogue ----------------
    const int cc = t & 63;                            // my float4 column group (fixed)
    const float4 bq = *(const float4*)(Bf + 4 * cc);

    // smem half (rows 128..255): direct, coalesced (512B/warp STG)
    #pragma unroll
    for (int k = 0; k < 32; k++) {
        int rc = k * 4 + (t >> 6);                    // row 0..127 (warp-uniform)
        __half2 h0 = Ksm2[rc * 132 + 2 * cc];
        __half2 h1 = Ksm2[rc * 132 + 2 * cc + 1];
        float ai = Af[128 + rc];
        float2 f0 = __half22float2(h0);
        float2 f1 = __half22float2(h1);
        float4 o;
        o.x = f0.x * ai * bq.x;
        o.y = f0.y * ai * bq.y;
        o.z = f1.x * ai * bq.z;
        o.w = f1.y * ai * bq.w;
        *(float4*)(om + (128 + rc) * NN + 4 * cc) = o;
    }
    // reg half (rows 0..127): via staging transpose, 2 chunks of 64 rows
    #pragma unroll
    for (int c = 0; c < 2; c++) {
        __syncthreads();
        if ((w >> 2) == c) {
            #pragma unroll
            for (int r = 0; r < 16; r++)
                stg4[(16 * (w & 3) + r) * 33 + l] = kv[r];    // conflict-free
        }
        __syncthreads();
        #pragma unroll
        for (int k = 0; k < 16; k++) {
            int rc = k * 4 + (t >> 6);                // row-in-chunk 0..63 (warp-uniform)
            __half2 h0 = stg2[rc * 132 + 2 * cc];
            __half2 h1 = stg2[rc * 132 + 2 * cc + 1];
            float ai = Af[c * 64 + rc];
            float2 f0 = __half22float2(h0);
            float2 f1 = __half22float2(h1);
            float4 o;
            o.x = f0.x * ai * bq.x;
            o.y = f0.y * ai * bq.y;
            o.z = f1.x * ai * bq.z;
            o.w = f1.y * ai * bq.w;
            *(float4*)(om + (c * 64 + rc) * NN + 4 * cc) = o;
        }
    }
}

extern "C" void kernel_launch(void* const* d_in, const int* in_sizes, int n_in,
                              void* d_out, int out_size) {
    const float* x = (const float*)d_in[0];
    float* out = (float*)d_out;
    int n_mat = in_sizes[0] / (NN * NN);      // 512
    cudaFuncSetAttribute(sinkhorn_kernel,
                         cudaFuncAttributeMaxDynamicSharedMemorySize, SM_BYTES);
    sinkhorn_kernel<<<n_mat, THREADS, SM_BYTES>>>(x, out);
}